// round 1
// baseline (speedup 1.0000x reference)
#include <cuda_runtime.h>
#include <math.h>

#define B_SZ   2048
#define K_OBJ  16
#define Z_SZ   128
#define D_IM   256
#define ROWS   (B_SZ * K_OBJ)      // 32768
#define NPAIR  120

// ---------------- scratch (device globals; no allocation allowed) ----------------
__device__ __align__(16) float g_zemb[(size_t)ROWS * 256];
__device__ __align__(16) float g_gi  [(size_t)ROWS * 384];
__device__ __align__(16) float g_gh  [(size_t)ROWS * 384];
__device__ __align__(16) float g_h   [(size_t)ROWS * 128];
__device__ __align__(16) float g_UV  [(size_t)ROWS * 1024];
__device__ __align__(16) float g_E   [(size_t)ROWS * 512];
__device__ __align__(16) float g_rel [(size_t)ROWS * 128];
__device__ __align__(16) float g_WUV [1024 * 128];
__device__ __align__(16) float g_WcE [128 * 640];
__device__ __align__(16) float g_Wstk[384 * 128];
__device__ __align__(16) float g_bstk[384];

// ---------------- weight prep kernels ----------------
// W_UV[0:512]   = We[:, 0:128] + We[:, 128:256]   (acts on h_i)
// W_UV[512:1024]= We[:, 256:384] + We[:, 384:512] (acts on h_j)
__global__ void prep_wuv(const float* __restrict__ We) {
    int idx = blockIdx.x * blockDim.x + threadIdx.x;
    if (idx >= 1024 * 128) return;
    int n = idx >> 7, c = idx & 127;
    float v;
    if (n < 512) v = We[n * 512 + c] + We[n * 512 + 128 + c];
    else {
        int nn = n - 512;
        v = We[nn * 512 + 256 + c] + We[nn * 512 + 384 + c];
    }
    g_WUV[idx] = v;
}

// WcE[:, 0:128]  = Wc[:, 0:128] + Wc[:, 128:256]  (acts on h)
// WcE[:, 128:640]= Wc[:, 256:768]                 (acts on E)
__global__ void prep_wc(const float* __restrict__ Wc) {
    int idx = blockIdx.x * blockDim.x + threadIdx.x;
    if (idx >= 128 * 640) return;
    int n = idx / 640, c = idx % 640;
    float v = (c < 128) ? (Wc[n * 768 + c] + Wc[n * 768 + 128 + c])
                        : Wc[n * 768 + 128 + c];   // 128+c == 256+(c-128)
    g_WcE[idx] = v;
}

__global__ void prep_wstk(const float* __restrict__ Wl, const float* __restrict__ bl,
                          const float* __restrict__ Wsc, const float* __restrict__ bs,
                          const float* __restrict__ Wh, const float* __restrict__ bh) {
    int idx = blockIdx.x * blockDim.x + threadIdx.x;
    if (idx < 384 * 128) {
        int n = idx >> 7, c = idx & 127;
        const float* W = (n < 128) ? Wl : ((n < 256) ? Wsc : Wh);
        g_Wstk[idx] = W[(n & 127) * 128 + c];
    }
    if (idx < 384) {
        const float* bb = (idx < 128) ? bl : ((idx < 256) ? bs : bh);
        g_bstk[idx] = bb[idx & 127];
    }
}

// ---------------- generic NT SGEMM: C[M,N] = act(X @ W^T + bias) ----------------
// 128x128x8 tiles, 256 threads, 8x8 per thread, vectorized smem.
// X is split: k < k1 -> X1 (ld1), else X2 (ld2, local col kk-k1). W is [N, Kd] row-major.
// ACT: 0 none, 1 elu.  SPLIT: 0 -> C[m*ldc+n];  1 -> n<256: C[m*256+n], else C2[m*128+n-256].
template <int ACT, int SPLIT>
__global__ void __launch_bounds__(256) sgemm_nt(
    const float* __restrict__ X1, int ld1, int k1,
    const float* __restrict__ X2, int ld2,
    const float* __restrict__ W, const float* __restrict__ bias,
    float* __restrict__ C, int ldc, float* __restrict__ C2, int Kd)
{
    __shared__ float sX[8][128];
    __shared__ float sW[8][128];
    const int bm = blockIdx.y * 128;
    const int bn = blockIdx.x * 128;
    const int tid = threadIdx.x;
    const int tx = tid & 15;
    const int ty = tid >> 4;
    const int lrow = tid >> 1;
    const int lkc = (tid & 1) * 4;

    float acc[8][8];
#pragma unroll
    for (int i = 0; i < 8; i++)
#pragma unroll
        for (int j = 0; j < 8; j++) acc[i][j] = 0.f;

    for (int k0 = 0; k0 < Kd; k0 += 8) {
        int kk = k0 + lkc;
        float4 xv;
        if (kk < k1) xv = *(const float4*)(X1 + (size_t)(bm + lrow) * ld1 + kk);
        else         xv = *(const float4*)(X2 + (size_t)(bm + lrow) * ld2 + (kk - k1));
        float4 wv = *(const float4*)(W + (size_t)(bn + lrow) * Kd + kk);
        sX[lkc + 0][lrow] = xv.x; sX[lkc + 1][lrow] = xv.y;
        sX[lkc + 2][lrow] = xv.z; sX[lkc + 3][lrow] = xv.w;
        sW[lkc + 0][lrow] = wv.x; sW[lkc + 1][lrow] = wv.y;
        sW[lkc + 2][lrow] = wv.z; sW[lkc + 3][lrow] = wv.w;
        __syncthreads();
#pragma unroll
        for (int k = 0; k < 8; k++) {
            float a[8], b[8];
            *(float4*)&a[0] = *(const float4*)&sX[k][ty * 4];
            *(float4*)&a[4] = *(const float4*)&sX[k][64 + ty * 4];
            *(float4*)&b[0] = *(const float4*)&sW[k][tx * 4];
            *(float4*)&b[4] = *(const float4*)&sW[k][64 + tx * 4];
#pragma unroll
            for (int i = 0; i < 8; i++)
#pragma unroll
                for (int j = 0; j < 8; j++) acc[i][j] += a[i] * b[j];
        }
        __syncthreads();
    }

#pragma unroll
    for (int i = 0; i < 8; i++) {
        int m = bm + ((i < 4) ? (ty * 4 + i) : (64 + ty * 4 + i - 4));
#pragma unroll
        for (int j = 0; j < 8; j++) {
            int n = bn + ((j < 4) ? (tx * 4 + j) : (64 + tx * 4 + j - 4));
            float v = acc[i][j];
            if (bias) v += bias[n];
            if (ACT == 1) v = (v > 0.f) ? v : expm1f(v);
            if (SPLIT) {
                if (n < 256) C[(size_t)m * 256 + n] = v;
                else         C2[(size_t)m * 128 + (n - 256)] = v;
            } else {
                C[(size_t)m * ldc + n] = v;
            }
        }
    }
}

// ---------------- GRU gate fusion ----------------
__device__ __forceinline__ float sigm(float x) { return 1.f / (1.f + expf(-x)); }

__global__ void gru_gate(const float* __restrict__ gi, const float* __restrict__ gh,
                         const float* __restrict__ h0, float* __restrict__ h) {
    int idx = blockIdx.x * blockDim.x + threadIdx.x;
    if (idx >= ROWS * 128) return;
    int m = idx >> 7, c = idx & 127;
    const float* gim = gi + (size_t)m * 384;
    const float* ghm = gh + (size_t)m * 384;
    float r = sigm(gim[c] + ghm[c]);
    float u = sigm(gim[128 + c] + ghm[128 + c]);
    float n = tanhf(gim[256 + c] + r * ghm[256 + c]);
    h[idx] = (1.f - u) * n + u * h0[idx];
}

// ---------------- pair stage: per batch element, all in smem ----------------
// eff[p] = elu(U[i] + V[j] + be); att = sigmoid(dot(eff, wa) + ba); E[i]+=att*eff; E[j]+=att*eff
__global__ void __launch_bounds__(512) pair_kernel(
    const float* __restrict__ UV, const float* __restrict__ Wa,
    const float* __restrict__ ba, const float* __restrict__ be,
    float* __restrict__ E)
{
    extern __shared__ float sm[];
    float* Ub  = sm;                 // 16*512
    float* Vb  = Ub + 16 * 512;      // 16*512
    float* Eb  = Vb + 16 * 512;      // 16*512
    float* was = Eb + 16 * 512;      // 512
    float* bes = was + 512;          // 512

    const int b = blockIdx.x;
    const int tid = threadIdx.x;

    for (int i = tid; i < 16 * 512; i += 512) {
        int k = i >> 9, t = i & 511;
        const float* row = UV + (size_t)(b * 16 + k) * 1024;
        Ub[i] = row[t];
        Vb[i] = row[512 + t];
        Eb[i] = 0.f;
    }
    was[tid & 511] = Wa[tid & 511];
    bes[tid & 511] = be[tid & 511];
    __syncthreads();

    const float ba0 = ba[0];
    const int wid = tid >> 5, lane = tid & 31;

    for (int p = wid; p < NPAIR; p += 16) {
        int ii = 0, rem = p, span = K_OBJ - 1;
        while (rem >= span) { rem -= span; ii++; span--; }
        int jj = ii + 1 + rem;

        const float* Ui = Ub + ii * 512;
        const float* Vj = Vb + jj * 512;
        float e[16];
        float dot = 0.f;
#pragma unroll
        for (int c = 0; c < 16; c++) {
            int t = lane + 32 * c;
            float x = Ui[t] + Vj[t] + bes[t];
            x = (x > 0.f) ? x : expm1f(x);
            e[c] = x;
            dot += x * was[t];
        }
#pragma unroll
        for (int o = 16; o > 0; o >>= 1) dot += __shfl_xor_sync(0xffffffffu, dot, o);
        float att = 1.f / (1.f + expf(-(dot + ba0)));

        float* Ei = Eb + ii * 512;
        float* Ej = Eb + jj * 512;
#pragma unroll
        for (int c = 0; c < 16; c++) {
            int t = lane + 32 * c;
            float w = att * e[c];
            atomicAdd(Ei + t, w);
            atomicAdd(Ej + t, w);
        }
    }
    __syncthreads();

    float* Eout = E + (size_t)b * 16 * 512;
    for (int i = tid; i < 16 * 512; i += 512) Eout[i] = Eb[i];
}

// ---------------- host launcher ----------------
extern "C" void kernel_launch(void* const* d_in, const int* in_sizes, int n_in,
                              void* d_out, int out_size)
{
    const float* z    = (const float*)d_in[0];
    const float* h0   = (const float*)d_in[1];
    const float* W_obj= (const float*)d_in[2];
    const float* b_obj= (const float*)d_in[3];
    const float* Wih  = (const float*)d_in[4];
    const float* bih  = (const float*)d_in[5];
    const float* Whh  = (const float*)d_in[6];
    const float* bhh  = (const float*)d_in[7];
    const float* We   = (const float*)d_in[8];
    const float* be   = (const float*)d_in[9];
    const float* Wa   = (const float*)d_in[10];
    const float* ba   = (const float*)d_in[11];
    const float* Wc   = (const float*)d_in[12];
    const float* bc   = (const float*)d_in[13];
    const float* Wl   = (const float*)d_in[14];
    const float* bl   = (const float*)d_in[15];
    const float* Wsc  = (const float*)d_in[16];
    const float* bs   = (const float*)d_in[17];
    const float* Wh   = (const float*)d_in[18];
    const float* bh   = (const float*)d_in[19];

    float* out1 = (float*)d_out;                       // [ROWS, 256] = concat(loc, scale)
    float* out2 = out1 + (size_t)ROWS * 256;           // [ROWS, 128] = h_out

    float *p_zemb, *p_gi, *p_gh, *p_h, *p_UV, *p_E, *p_rel;
    float *p_WUV, *p_WcE, *p_Wstk, *p_bstk;
    cudaGetSymbolAddress((void**)&p_zemb, g_zemb);
    cudaGetSymbolAddress((void**)&p_gi,   g_gi);
    cudaGetSymbolAddress((void**)&p_gh,   g_gh);
    cudaGetSymbolAddress((void**)&p_h,    g_h);
    cudaGetSymbolAddress((void**)&p_UV,   g_UV);
    cudaGetSymbolAddress((void**)&p_E,    g_E);
    cudaGetSymbolAddress((void**)&p_rel,  g_rel);
    cudaGetSymbolAddress((void**)&p_WUV,  g_WUV);
    cudaGetSymbolAddress((void**)&p_WcE,  g_WcE);
    cudaGetSymbolAddress((void**)&p_Wstk, g_Wstk);
    cudaGetSymbolAddress((void**)&p_bstk, g_bstk);

    // weight folding
    prep_wuv <<<(1024 * 128 + 255) / 256, 256>>>(We);
    prep_wc  <<<(128 * 640 + 255) / 256, 256>>>(Wc);
    prep_wstk<<<(384 * 128 + 255) / 256, 256>>>(Wl, bl, Wsc, bs, Wh, bh);

    const int MB = ROWS / 128;   // 256

    // G1: z_embed = elu(z @ W_obj^T + b_obj)   [ROWS, 256]
    sgemm_nt<1, 0><<<dim3(256 / 128, MB), 256>>>(z, 128, 128, nullptr, 0,
                                                 W_obj, b_obj, p_zemb, 256, nullptr, 128);
    // G2a: gi = z_embed @ Wih^T + bih          [ROWS, 384]
    sgemm_nt<0, 0><<<dim3(384 / 128, MB), 256>>>(p_zemb, 256, 256, nullptr, 0,
                                                 Wih, bih, p_gi, 384, nullptr, 256);
    // G2b: gh = h0 @ Whh^T + bhh               [ROWS, 384]
    sgemm_nt<0, 0><<<dim3(384 / 128, MB), 256>>>(h0, 128, 128, nullptr, 0,
                                                 Whh, bhh, p_gh, 384, nullptr, 128);
    // GRU gates -> h_new
    gru_gate<<<(ROWS * 128 + 255) / 256, 256>>>(p_gi, p_gh, h0, p_h);

    // G3: UV = h_new @ W_UV^T  (U cols 0:512, V cols 512:1024)
    sgemm_nt<0, 0><<<dim3(1024 / 128, MB), 256>>>(p_h, 128, 128, nullptr, 0,
                                                  p_WUV, nullptr, p_UV, 1024, nullptr, 128);

    // pair stage -> E [ROWS, 512]
    size_t smem = (3 * 16 * 512 + 1024) * sizeof(float);  // 102400 B
    cudaFuncSetAttribute(pair_kernel, cudaFuncAttributeMaxDynamicSharedMemorySize, (int)smem);
    pair_kernel<<<B_SZ, 512, smem>>>(p_UV, Wa, ba, be, p_E);

    // G4: rel = [h_new | E] @ WcE^T + bc       [ROWS, 128], Kd = 640, split at 128
    sgemm_nt<0, 0><<<dim3(128 / 128, MB), 256>>>(p_h, 128, 128, p_E, 512,
                                                 p_WcE, bc, p_rel, 128, nullptr, 640);

    // G5: [loc|scale|h_out] = rel @ Wstk^T + bstk, split-written to out1/out2
    sgemm_nt<0, 1><<<dim3(384 / 128, MB), 256>>>(p_rel, 128, 128, nullptr, 0,
                                                 p_Wstk, p_bstk, out1, 0, out2, 128);
}

// round 3
// speedup vs baseline: 1.0957x; 1.0957x over previous
#include <cuda_runtime.h>
#include <math.h>
#include <stdint.h>

#define B_SZ   2048
#define K_OBJ  16
#define ROWS   (B_SZ * K_OBJ)      // 32768
#define NPAIR  120

// ---------------- scratch (device globals; no allocation allowed) ----------------
__device__ __align__(16) float g_zemb[(size_t)ROWS * 256];
__device__ __align__(16) float g_gi  [(size_t)ROWS * 384];
__device__ __align__(16) float g_gh  [(size_t)ROWS * 384];
__device__ __align__(16) float g_h   [(size_t)ROWS * 128];
__device__ __align__(16) float g_UV  [(size_t)ROWS * 1024];
__device__ __align__(16) float g_E   [(size_t)ROWS * 512];
__device__ __align__(16) float g_rel [(size_t)ROWS * 128];
__device__ __align__(16) float g_WUV [1024 * 128];
__device__ __align__(16) float g_WcE [128 * 640];
__device__ __align__(16) float g_Wstk[384 * 128];
__device__ __align__(16) float g_bstk[384];

// ---------------- tf32 helpers ----------------
__device__ __forceinline__ void tf32split(float x, uint32_t& h, uint32_t& l) {
    asm("cvt.rna.tf32.f32 %0, %1;" : "=r"(h) : "f"(x));
    float lf = x - __uint_as_float(h);
    asm("cvt.rna.tf32.f32 %0, %1;" : "=r"(l) : "f"(lf));
}

__device__ __forceinline__ void mma8(float* d, const uint32_t* a, const uint32_t* b) {
    asm volatile(
        "mma.sync.aligned.m16n8k8.row.col.f32.tf32.tf32.f32 "
        "{%0,%1,%2,%3}, {%4,%5,%6,%7}, {%8,%9}, {%0,%1,%2,%3};"
        : "+f"(d[0]), "+f"(d[1]), "+f"(d[2]), "+f"(d[3])
        : "r"(a[0]), "r"(a[1]), "r"(a[2]), "r"(a[3]), "r"(b[0]), "r"(b[1]));
}

// ---------------- tensor-core tf32 (3-pass split) NT GEMM ----------------
// C[M,N] = act(X @ W^T + bias); X split at k1 between X1(ld1)/X2(ld2); W [N,Kd] row-major.
// CTA tile 128x128, K-slab 16, 8 warps each 32(M)x64(N).
// smem layout [k][m] (or [k][n]) with stride 136 floats -> conflict-free frag LDS.
// ACT: 0 none, 1 elu. SPLIT: 0 normal; 1 -> n<256 into C(ld 256), n>=256 into C2(ld 128).
#define SSTRIDE 136

template <int ACT, int SPLIT>
__global__ void __launch_bounds__(256, 2) gemm_mma(
    const float* __restrict__ X1, int ld1, int k1,
    const float* __restrict__ X2, int ld2,
    const float* __restrict__ W, const float* __restrict__ bias,
    float* __restrict__ C, int ldc, float* __restrict__ C2, int Kd)
{
    __shared__ uint32_t sAhi[16 * SSTRIDE];
    __shared__ uint32_t sAlo[16 * SSTRIDE];
    __shared__ uint32_t sBhi[16 * SSTRIDE];
    __shared__ uint32_t sBlo[16 * SSTRIDE];

    const int tid = threadIdx.x;
    const int lane = tid & 31;
    const int wid = tid >> 5;
    const int warp_m = wid >> 1;       // 0..3
    const int warp_n = wid & 1;        // 0..1
    const int gid = lane >> 2;         // 0..7
    const int tig = lane & 3;          // 0..3
    const int bm = blockIdx.y * 128;
    const int bn = blockIdx.x * 128;

    float acc[2][8][4];
#pragma unroll
    for (int mi = 0; mi < 2; mi++)
#pragma unroll
        for (int nf = 0; nf < 8; nf++)
#pragma unroll
            for (int e = 0; e < 4; e++) acc[mi][nf][e] = 0.f;

#pragma unroll 1
    for (int k0 = 0; k0 < Kd; k0 += 16) {
        const float* xp; int xld, xc;
        if (k0 < k1) { xp = X1; xld = ld1; xc = k0; }
        else         { xp = X2; xld = ld2; xc = k0 - k1; }

        __syncthreads();
#pragma unroll
        for (int j = 0; j < 2; j++) {
            int idx = j * 256 + tid;
            int kcl = idx >> 7;        // 0..3 -> k chunk of 4
            int m   = idx & 127;
            float4 va = *(const float4*)(xp + (size_t)(bm + m) * xld + xc + kcl * 4);
            float4 vb = *(const float4*)(W  + (size_t)(bn + m) * Kd  + k0 + kcl * 4);
            float av[4] = {va.x, va.y, va.z, va.w};
            float bv[4] = {vb.x, vb.y, vb.z, vb.w};
#pragma unroll
            for (int e = 0; e < 4; e++) {
                uint32_t h, l;
                tf32split(av[e], h, l);
                sAhi[(kcl * 4 + e) * SSTRIDE + m] = h;
                sAlo[(kcl * 4 + e) * SSTRIDE + m] = l;
                tf32split(bv[e], h, l);
                sBhi[(kcl * 4 + e) * SSTRIDE + m] = h;
                sBlo[(kcl * 4 + e) * SSTRIDE + m] = l;
            }
        }
        __syncthreads();

#pragma unroll
        for (int ks = 0; ks < 2; ks++) {
            const int kb = ks * 8 + tig;
            uint32_t ah[2][4], al[2][4];
#pragma unroll
            for (int mi = 0; mi < 2; mi++) {
                int am = warp_m * 32 + mi * 16 + gid;
                ah[mi][0] = sAhi[kb * SSTRIDE + am];
                ah[mi][1] = sAhi[kb * SSTRIDE + am + 8];
                ah[mi][2] = sAhi[(kb + 4) * SSTRIDE + am];
                ah[mi][3] = sAhi[(kb + 4) * SSTRIDE + am + 8];
                al[mi][0] = sAlo[kb * SSTRIDE + am];
                al[mi][1] = sAlo[kb * SSTRIDE + am + 8];
                al[mi][2] = sAlo[(kb + 4) * SSTRIDE + am];
                al[mi][3] = sAlo[(kb + 4) * SSTRIDE + am + 8];
            }
            uint32_t bf[8][2];
#pragma unroll
            for (int nf = 0; nf < 8; nf++) {
                int an = warp_n * 64 + nf * 8 + gid;
                bf[nf][0] = sBhi[kb * SSTRIDE + an];
                bf[nf][1] = sBhi[(kb + 4) * SSTRIDE + an];
            }
            // hi*hi and lo*hi
#pragma unroll
            for (int mi = 0; mi < 2; mi++)
#pragma unroll
                for (int nf = 0; nf < 8; nf++) {
                    mma8(acc[mi][nf], ah[mi], bf[nf]);
                    mma8(acc[mi][nf], al[mi], bf[nf]);
                }
            // hi*lo (reuse bf regs)
#pragma unroll
            for (int nf = 0; nf < 8; nf++) {
                int an = warp_n * 64 + nf * 8 + gid;
                bf[nf][0] = sBlo[kb * SSTRIDE + an];
                bf[nf][1] = sBlo[(kb + 4) * SSTRIDE + an];
            }
#pragma unroll
            for (int mi = 0; mi < 2; mi++)
#pragma unroll
                for (int nf = 0; nf < 8; nf++)
                    mma8(acc[mi][nf], ah[mi], bf[nf]);
        }
    }

    // ---- epilogue ----
    float* outp; int oldc, ncol0;
    if (SPLIT) {
        if (bn >= 256) { outp = C2; oldc = 128; ncol0 = bn - 256; }
        else           { outp = C;  oldc = 256; ncol0 = bn; }
    } else { outp = C; oldc = ldc; ncol0 = bn; }

#pragma unroll
    for (int mi = 0; mi < 2; mi++) {
        int r0 = bm + warp_m * 32 + mi * 16 + gid;
#pragma unroll
        for (int nf = 0; nf < 8; nf++) {
            int cg = bn + warp_n * 64 + nf * 8 + tig * 2;   // global col (bias index)
            int cl = ncol0 + warp_n * 64 + nf * 8 + tig * 2;
            float b0 = 0.f, b1 = 0.f;
            if (bias) { float2 bv = *(const float2*)(bias + cg); b0 = bv.x; b1 = bv.y; }
            float v00 = acc[mi][nf][0] + b0;
            float v01 = acc[mi][nf][1] + b1;
            float v10 = acc[mi][nf][2] + b0;
            float v11 = acc[mi][nf][3] + b1;
            if (ACT == 1) {
                v00 = (v00 > 0.f) ? v00 : expm1f(v00);
                v01 = (v01 > 0.f) ? v01 : expm1f(v01);
                v10 = (v10 > 0.f) ? v10 : expm1f(v10);
                v11 = (v11 > 0.f) ? v11 : expm1f(v11);
            }
            *(float2*)(outp + (size_t)r0 * oldc + cl)       = make_float2(v00, v01);
            *(float2*)(outp + (size_t)(r0 + 8) * oldc + cl) = make_float2(v10, v11);
        }
    }
}

// ---------------- weight prep kernels ----------------
__global__ void prep_wuv(const float* __restrict__ We) {
    int idx = blockIdx.x * blockDim.x + threadIdx.x;
    if (idx >= 1024 * 128) return;
    int n = idx >> 7, c = idx & 127;
    float v;
    if (n < 512) v = We[n * 512 + c] + We[n * 512 + 128 + c];
    else {
        int nn = n - 512;
        v = We[nn * 512 + 256 + c] + We[nn * 512 + 384 + c];
    }
    g_WUV[idx] = v;
}

__global__ void prep_wc(const float* __restrict__ Wc) {
    int idx = blockIdx.x * blockDim.x + threadIdx.x;
    if (idx >= 128 * 640) return;
    int n = idx / 640, c = idx % 640;
    float v = (c < 128) ? (Wc[n * 768 + c] + Wc[n * 768 + 128 + c])
                        : Wc[n * 768 + 128 + c];
    g_WcE[idx] = v;
}

__global__ void prep_wstk(const float* __restrict__ Wl, const float* __restrict__ bl,
                          const float* __restrict__ Wsc, const float* __restrict__ bs,
                          const float* __restrict__ Wh, const float* __restrict__ bh) {
    int idx = blockIdx.x * blockDim.x + threadIdx.x;
    if (idx < 384 * 128) {
        int n = idx >> 7, c = idx & 127;
        const float* W = (n < 128) ? Wl : ((n < 256) ? Wsc : Wh);
        g_Wstk[idx] = W[(n & 127) * 128 + c];
    }
    if (idx < 384) {
        const float* bb = (idx < 128) ? bl : ((idx < 256) ? bs : bh);
        g_bstk[idx] = bb[idx & 127];
    }
}

// ---------------- GRU gate fusion ----------------
__device__ __forceinline__ float sigm(float x) { return 1.f / (1.f + expf(-x)); }

__global__ void gru_gate(const float* __restrict__ gi, const float* __restrict__ gh,
                         const float* __restrict__ h0, float* __restrict__ h) {
    int idx = blockIdx.x * blockDim.x + threadIdx.x;
    if (idx >= ROWS * 128) return;
    int m = idx >> 7, c = idx & 127;
    const float* gim = gi + (size_t)m * 384;
    const float* ghm = gh + (size_t)m * 384;
    float r = sigm(gim[c] + ghm[c]);
    float u = sigm(gim[128 + c] + ghm[128 + c]);
    float n = tanhf(gim[256 + c] + r * ghm[256 + c]);
    h[idx] = (1.f - u) * n + u * h0[idx];
}

// ---------------- pair stage ----------------
__global__ void __launch_bounds__(512) pair_kernel(
    const float* __restrict__ UV, const float* __restrict__ Wa,
    const float* __restrict__ ba, const float* __restrict__ be,
    float* __restrict__ E)
{
    extern __shared__ float smf[];
    float* Ub  = smf;
    float* Vb  = Ub + 16 * 512;
    float* Eb  = Vb + 16 * 512;
    float* was = Eb + 16 * 512;
    float* bes = was + 512;

    const int b = blockIdx.x;
    const int tid = threadIdx.x;

    for (int i = tid; i < 16 * 512; i += 512) {
        int k = i >> 9, t = i & 511;
        const float* row = UV + (size_t)(b * 16 + k) * 1024;
        Ub[i] = row[t];
        Vb[i] = row[512 + t];
        Eb[i] = 0.f;
    }
    was[tid & 511] = Wa[tid & 511];
    bes[tid & 511] = be[tid & 511];
    __syncthreads();

    const float ba0 = ba[0];
    const int wid = tid >> 5, lane = tid & 31;

    for (int p = wid; p < NPAIR; p += 16) {
        int ii = 0, rem = p, span = K_OBJ - 1;
        while (rem >= span) { rem -= span; ii++; span--; }
        int jj = ii + 1 + rem;

        const float* Ui = Ub + ii * 512;
        const float* Vj = Vb + jj * 512;
        float e[16];
        float dot = 0.f;
#pragma unroll
        for (int c = 0; c < 16; c++) {
            int t = lane + 32 * c;
            float x = Ui[t] + Vj[t] + bes[t];
            x = (x > 0.f) ? x : expm1f(x);
            e[c] = x;
            dot += x * was[t];
        }
#pragma unroll
        for (int o = 16; o > 0; o >>= 1) dot += __shfl_xor_sync(0xffffffffu, dot, o);
        float att = 1.f / (1.f + expf(-(dot + ba0)));

        float* Ei = Eb + ii * 512;
        float* Ej = Eb + jj * 512;
#pragma unroll
        for (int c = 0; c < 16; c++) {
            int t = lane + 32 * c;
            float w = att * e[c];
            atomicAdd(Ei + t, w);
            atomicAdd(Ej + t, w);
        }
    }
    __syncthreads();

    float* Eout = E + (size_t)b * 16 * 512;
    for (int i = tid; i < 16 * 512; i += 512) Eout[i] = Eb[i];
}

// ---------------- host launcher ----------------
extern "C" void kernel_launch(void* const* d_in, const int* in_sizes, int n_in,
                              void* d_out, int out_size)
{
    const float* z    = (const float*)d_in[0];
    const float* h0   = (const float*)d_in[1];
    const float* W_obj= (const float*)d_in[2];
    const float* b_obj= (const float*)d_in[3];
    const float* Wih  = (const float*)d_in[4];
    const float* bih  = (const float*)d_in[5];
    const float* Whh  = (const float*)d_in[6];
    const float* bhh  = (const float*)d_in[7];
    const float* We   = (const float*)d_in[8];
    const float* be   = (const float*)d_in[9];
    const float* Wa   = (const float*)d_in[10];
    const float* ba   = (const float*)d_in[11];
    const float* Wc   = (const float*)d_in[12];
    const float* bc   = (const float*)d_in[13];
    const float* Wl   = (const float*)d_in[14];
    const float* bl   = (const float*)d_in[15];
    const float* Wsc  = (const float*)d_in[16];
    const float* bs   = (const float*)d_in[17];
    const float* Wh   = (const float*)d_in[18];
    const float* bh   = (const float*)d_in[19];

    float* out1 = (float*)d_out;                       // [ROWS, 256] = concat(loc, scale)
    float* out2 = out1 + (size_t)ROWS * 256;           // [ROWS, 128] = h_out

    float *p_zemb, *p_gi, *p_gh, *p_h, *p_UV, *p_E, *p_rel;
    float *p_WUV, *p_WcE, *p_Wstk, *p_bstk;
    cudaGetSymbolAddress((void**)&p_zemb, g_zemb);
    cudaGetSymbolAddress((void**)&p_gi,   g_gi);
    cudaGetSymbolAddress((void**)&p_gh,   g_gh);
    cudaGetSymbolAddress((void**)&p_h,    g_h);
    cudaGetSymbolAddress((void**)&p_UV,   g_UV);
    cudaGetSymbolAddress((void**)&p_E,    g_E);
    cudaGetSymbolAddress((void**)&p_rel,  g_rel);
    cudaGetSymbolAddress((void**)&p_WUV,  g_WUV);
    cudaGetSymbolAddress((void**)&p_WcE,  g_WcE);
    cudaGetSymbolAddress((void**)&p_Wstk, g_Wstk);
    cudaGetSymbolAddress((void**)&p_bstk, g_bstk);

    // weight folding
    prep_wuv <<<(1024 * 128 + 255) / 256, 256>>>(We);
    prep_wc  <<<(128 * 640 + 255) / 256, 256>>>(Wc);
    prep_wstk<<<(384 * 128 + 255) / 256, 256>>>(Wl, bl, Wsc, bs, Wh, bh);

    const int MB = ROWS / 128;   // 256

    // G1: z_embed = elu(z @ W_obj^T + b_obj)   [ROWS, 256]
    gemm_mma<1,0><<<dim3(2, MB), 256>>>(z, 128, 128, nullptr, 0,
                                        W_obj, b_obj, p_zemb, 256, nullptr, 128);
    // G2a: gi = z_embed @ Wih^T + bih          [ROWS, 384]
    gemm_mma<0,0><<<dim3(3, MB), 256>>>(p_zemb, 256, 256, nullptr, 0,
                                        Wih, bih, p_gi, 384, nullptr, 256);
    // G2b: gh = h0 @ Whh^T + bhh               [ROWS, 384]
    gemm_mma<0,0><<<dim3(3, MB), 256>>>(h0, 128, 128, nullptr, 0,
                                        Whh, bhh, p_gh, 384, nullptr, 128);
    // GRU gates -> h_new
    gru_gate<<<(ROWS * 128 + 255) / 256, 256>>>(p_gi, p_gh, h0, p_h);

    // G3: UV = h_new @ W_UV^T                  [ROWS, 1024]
    gemm_mma<0,0><<<dim3(8, MB), 256>>>(p_h, 128, 128, nullptr, 0,
                                        p_WUV, nullptr, p_UV, 1024, nullptr, 128);

    // pair stage -> E [ROWS, 512]
    size_t psmem = (3 * 16 * 512 + 1024) * sizeof(float);
    cudaFuncSetAttribute(pair_kernel, cudaFuncAttributeMaxDynamicSharedMemorySize, (int)psmem);
    pair_kernel<<<B_SZ, 512, psmem>>>(p_UV, Wa, ba, be, p_E);

    // G4: rel = [h_new | E] @ WcE^T + bc       [ROWS, 128], Kd = 640
    gemm_mma<0,0><<<dim3(1, MB), 256>>>(p_h, 128, 128, p_E, 512,
                                        p_WcE, bc, p_rel, 128, nullptr, 640);

    // G5: [loc|scale|h_out] = rel @ Wstk^T + bstk, split output
    gemm_mma<0,1><<<dim3(3, MB), 256>>>(p_rel, 128, 128, nullptr, 0,
                                        p_Wstk, p_bstk, out1, 0, out2, 128);
}

// round 4
// speedup vs baseline: 1.1441x; 1.0441x over previous
#include <cuda_runtime.h>
#include <math.h>
#include <stdint.h>

#define B_SZ   2048
#define K_OBJ  16
#define ROWS   (B_SZ * K_OBJ)      // 32768
#define NPAIR  120

// ---------------- scratch (device globals; no allocation allowed) ----------------
// tf32-split activation buffers (hi/lo pairs)
__device__ __align__(16) uint32_t g_z_hi  [(size_t)ROWS * 128];
__device__ __align__(16) uint32_t g_z_lo  [(size_t)ROWS * 128];
__device__ __align__(16) uint32_t g_h0_hi [(size_t)ROWS * 128];
__device__ __align__(16) uint32_t g_h0_lo [(size_t)ROWS * 128];
__device__ __align__(16) uint32_t g_ze_hi [(size_t)ROWS * 256];
__device__ __align__(16) uint32_t g_ze_lo [(size_t)ROWS * 256];
__device__ __align__(16) uint32_t g_h_hi  [(size_t)ROWS * 128];
__device__ __align__(16) uint32_t g_h_lo  [(size_t)ROWS * 128];
__device__ __align__(16) uint32_t g_E_hi  [(size_t)ROWS * 512];
__device__ __align__(16) uint32_t g_E_lo  [(size_t)ROWS * 512];
__device__ __align__(16) uint32_t g_rel_hi[(size_t)ROWS * 128];
__device__ __align__(16) uint32_t g_rel_lo[(size_t)ROWS * 128];
// f32 intermediates consumed by elementwise kernels
__device__ __align__(16) float g_gi [(size_t)ROWS * 384];
__device__ __align__(16) float g_gh [(size_t)ROWS * 384];
__device__ __align__(16) float g_UV [(size_t)ROWS * 1024];
// split weights
__device__ __align__(16) uint32_t g_Wobj_hi[256 * 128],  g_Wobj_lo[256 * 128];
__device__ __align__(16) uint32_t g_Wih_hi [384 * 256],  g_Wih_lo [384 * 256];
__device__ __align__(16) uint32_t g_Whh_hi [384 * 128],  g_Whh_lo [384 * 128];
__device__ __align__(16) uint32_t g_WUV_hi [1024 * 128], g_WUV_lo [1024 * 128];
__device__ __align__(16) uint32_t g_WcE_hi [128 * 640],  g_WcE_lo [128 * 640];
__device__ __align__(16) uint32_t g_Wstk_hi[384 * 128],  g_Wstk_lo[384 * 128];
__device__ __align__(16) float    g_bstk[384];

// ---------------- helpers ----------------
__device__ __forceinline__ void tf32split(float x, uint32_t& h, uint32_t& l) {
    asm("cvt.rna.tf32.f32 %0, %1;" : "=r"(h) : "f"(x));
    float lf = x - __uint_as_float(h);
    asm("cvt.rna.tf32.f32 %0, %1;" : "=r"(l) : "f"(lf));
}

__device__ __forceinline__ uint32_t smem_u32(const void* p) {
    uint32_t a;
    asm("{ .reg .u64 t; cvta.to.shared.u64 t, %1; cvt.u32.u64 %0, t; }" : "=r"(a) : "l"(p));
    return a;
}

__device__ __forceinline__ void cp16(uint32_t dst, const void* src) {
    asm volatile("cp.async.ca.shared.global [%0], [%1], 16;" :: "r"(dst), "l"(src) : "memory");
}
#define CP_COMMIT() asm volatile("cp.async.commit_group;" ::: "memory")
#define CP_WAIT(n)  asm volatile("cp.async.wait_group %0;" :: "n"(n) : "memory")

__device__ __forceinline__ void mma8(float* d, const uint32_t* a, const uint32_t* b) {
    asm volatile(
        "mma.sync.aligned.m16n8k8.row.col.f32.tf32.tf32.f32 "
        "{%0,%1,%2,%3}, {%4,%5,%6,%7}, {%8,%9}, {%0,%1,%2,%3};"
        : "+f"(d[0]), "+f"(d[1]), "+f"(d[2]), "+f"(d[3])
        : "r"(a[0]), "r"(a[1]), "r"(a[2]), "r"(a[3]), "r"(b[0]), "r"(b[1]));
}

// ---------------- tensor-core tf32x3 NT GEMM, pre-split operands ----------------
// C[M,N] = act(X @ W^T + bias); X split at k1 between X1(ld1)/X2(ld2); W [N,Kd] row-major.
// All operands pre-split into tf32 hi/lo. CTA tile 128x128, K-slab 16, 2-stage cp.async pipeline.
// smem per stage: 4 tiles (Ahi,Alo,Bhi,Blo) of 128x16 at [m][k] pad-20 -> 40960 B; 2 stages = 81920 B.
// OUTM: 0 = f32 C; 1 = tf32-split (Chi, Clo); 2 = final (n<256 -> C f32 ld256, else C2 f32 ld128).
#define PADK 20
#define STG_WORDS 10240   // 4 * 128 * PADK

template <int ACT, int OUTM>
__global__ void __launch_bounds__(256, 2) gemm_mma(
    const uint32_t* __restrict__ X1hi, const uint32_t* __restrict__ X1lo, int ld1, int k1,
    const uint32_t* __restrict__ X2hi, const uint32_t* __restrict__ X2lo, int ld2,
    const uint32_t* __restrict__ Whi, const uint32_t* __restrict__ Wlo,
    const float* __restrict__ bias,
    float* __restrict__ C, uint32_t* __restrict__ Chi, uint32_t* __restrict__ Clo,
    int ldc, float* __restrict__ C2, int Kd)
{
    extern __shared__ uint32_t smw[];
    const uint32_t sb = smem_u32(smw);

    const int tid = threadIdx.x;
    const int lane = tid & 31;
    const int wid = tid >> 5;
    const int warp_m = wid >> 1;
    const int warp_n = wid & 1;
    const int gid = lane >> 2;
    const int tig = lane & 3;
    const int bm = blockIdx.y * 128;
    const int bn = blockIdx.x * 128;

    float acc[2][8][4];
#pragma unroll
    for (int mi = 0; mi < 2; mi++)
#pragma unroll
        for (int nf = 0; nf < 8; nf++)
#pragma unroll
            for (int e = 0; e < 4; e++) acc[mi][nf][e] = 0.f;

    // loader: one K-slab (16 cols) into stage s
    auto load_slab = [&](int k0, int s) {
        const uint32_t *ahi, *alo; int xld, xc;
        if (k0 < k1) { ahi = X1hi; alo = X1lo; xld = ld1; xc = k0; }
        else         { ahi = X2hi; alo = X2lo; xld = ld2; xc = k0 - k1; }
        const uint32_t st = sb + s * (STG_WORDS * 4);
#pragma unroll
        for (int j = 0; j < 2; j++) {
            int c = j * 256 + tid;          // 0..511
            int m = c >> 2, kc = (c & 3) << 2;
            uint32_t so = (uint32_t)(m * PADK + kc) * 4;
            const size_t ga = (size_t)(bm + m) * xld + xc + kc;
            const size_t gw = (size_t)(bn + m) * Kd + k0 + kc;
            cp16(st + so,         ahi + ga);
            cp16(st + 10240 + so, alo + ga);
            cp16(st + 20480 + so, Whi + gw);
            cp16(st + 30720 + so, Wlo + gw);
        }
    };

    int s = 0;
    load_slab(0, 0);
    CP_COMMIT();

#pragma unroll 1
    for (int k0 = 0; k0 < Kd; k0 += 16) {
        if (k0 + 16 < Kd) {
            load_slab(k0 + 16, s ^ 1);
            CP_COMMIT();
            CP_WAIT(1);
        } else {
            CP_WAIT(0);
        }
        __syncthreads();

        const uint32_t* sA  = smw + s * STG_WORDS;
        const uint32_t* sAl = sA + 2560;
        const uint32_t* sB  = sA + 5120;
        const uint32_t* sBl = sA + 7680;

#pragma unroll
        for (int ks = 0; ks < 2; ks++) {
            const int kb = ks * 8 + tig;
            uint32_t ah[2][4], al[2][4];
#pragma unroll
            for (int mi = 0; mi < 2; mi++) {
                int am = (warp_m * 32 + mi * 16 + gid) * PADK;
                ah[mi][0] = sA [am + kb];
                ah[mi][1] = sA [am + 8 * PADK + kb];
                ah[mi][2] = sA [am + kb + 4];
                ah[mi][3] = sA [am + 8 * PADK + kb + 4];
                al[mi][0] = sAl[am + kb];
                al[mi][1] = sAl[am + 8 * PADK + kb];
                al[mi][2] = sAl[am + kb + 4];
                al[mi][3] = sAl[am + 8 * PADK + kb + 4];
            }
            uint32_t bf[8][2];
#pragma unroll
            for (int nf = 0; nf < 8; nf++) {
                int an = (warp_n * 64 + nf * 8 + gid) * PADK;
                bf[nf][0] = sB[an + kb];
                bf[nf][1] = sB[an + kb + 4];
            }
#pragma unroll
            for (int mi = 0; mi < 2; mi++)
#pragma unroll
                for (int nf = 0; nf < 8; nf++) {
                    mma8(acc[mi][nf], ah[mi], bf[nf]);
                    mma8(acc[mi][nf], al[mi], bf[nf]);
                }
#pragma unroll
            for (int nf = 0; nf < 8; nf++) {
                int an = (warp_n * 64 + nf * 8 + gid) * PADK;
                bf[nf][0] = sBl[an + kb];
                bf[nf][1] = sBl[an + kb + 4];
            }
#pragma unroll
            for (int mi = 0; mi < 2; mi++)
#pragma unroll
                for (int nf = 0; nf < 8; nf++)
                    mma8(acc[mi][nf], ah[mi], bf[nf]);
        }
        __syncthreads();
        s ^= 1;
    }

    // ---- epilogue ----
    float* outp = C; int oldc = ldc, ncol0 = bn;
    if (OUTM == 2) {
        if (bn >= 256) { outp = C2; oldc = 128; ncol0 = bn - 256; }
        else           { outp = C;  oldc = 256; ncol0 = bn; }
    }

#pragma unroll
    for (int mi = 0; mi < 2; mi++) {
        int r0 = bm + warp_m * 32 + mi * 16 + gid;
#pragma unroll
        for (int nf = 0; nf < 8; nf++) {
            int cg = bn + warp_n * 64 + nf * 8 + tig * 2;
            int cl = ncol0 + warp_n * 64 + nf * 8 + tig * 2;
            float b0 = 0.f, b1 = 0.f;
            if (bias) { float2 bv = *(const float2*)(bias + cg); b0 = bv.x; b1 = bv.y; }
            float v00 = acc[mi][nf][0] + b0;
            float v01 = acc[mi][nf][1] + b1;
            float v10 = acc[mi][nf][2] + b0;
            float v11 = acc[mi][nf][3] + b1;
            if (ACT == 1) {
                v00 = (v00 > 0.f) ? v00 : expm1f(v00);
                v01 = (v01 > 0.f) ? v01 : expm1f(v01);
                v10 = (v10 > 0.f) ? v10 : expm1f(v10);
                v11 = (v11 > 0.f) ? v11 : expm1f(v11);
            }
            if (OUTM == 1) {
                uint32_t h00, l00, h01, l01, h10, l10, h11, l11;
                tf32split(v00, h00, l00); tf32split(v01, h01, l01);
                tf32split(v10, h10, l10); tf32split(v11, h11, l11);
                *(uint2*)(Chi + (size_t)r0 * ldc + cl)       = make_uint2(h00, h01);
                *(uint2*)(Clo + (size_t)r0 * ldc + cl)       = make_uint2(l00, l01);
                *(uint2*)(Chi + (size_t)(r0 + 8) * ldc + cl) = make_uint2(h10, h11);
                *(uint2*)(Clo + (size_t)(r0 + 8) * ldc + cl) = make_uint2(l10, l11);
            } else {
                *(float2*)(outp + (size_t)r0 * oldc + cl)       = make_float2(v00, v01);
                *(float2*)(outp + (size_t)(r0 + 8) * oldc + cl) = make_float2(v10, v11);
            }
        }
    }
}

// ---------------- split / prep kernels ----------------
__global__ void split_f32(const float* __restrict__ src, uint32_t* __restrict__ hi,
                          uint32_t* __restrict__ lo, int n) {
    int idx = blockIdx.x * blockDim.x + threadIdx.x;
    if (idx >= n) return;
    uint32_t h, l;
    tf32split(src[idx], h, l);
    hi[idx] = h; lo[idx] = l;
}

__global__ void prep_wuv(const float* __restrict__ We) {
    int idx = blockIdx.x * blockDim.x + threadIdx.x;
    if (idx >= 1024 * 128) return;
    int n = idx >> 7, c = idx & 127;
    float v;
    if (n < 512) v = We[n * 512 + c] + We[n * 512 + 128 + c];
    else {
        int nn = n - 512;
        v = We[nn * 512 + 256 + c] + We[nn * 512 + 384 + c];
    }
    uint32_t h, l; tf32split(v, h, l);
    g_WUV_hi[idx] = h; g_WUV_lo[idx] = l;
}

__global__ void prep_wc(const float* __restrict__ Wc) {
    int idx = blockIdx.x * blockDim.x + threadIdx.x;
    if (idx >= 128 * 640) return;
    int n = idx / 640, c = idx % 640;
    float v = (c < 128) ? (Wc[n * 768 + c] + Wc[n * 768 + 128 + c])
                        : Wc[n * 768 + 128 + c];
    uint32_t h, l; tf32split(v, h, l);
    g_WcE_hi[idx] = h; g_WcE_lo[idx] = l;
}

__global__ void prep_wstk(const float* __restrict__ Wl, const float* __restrict__ bl,
                          const float* __restrict__ Wsc, const float* __restrict__ bs,
                          const float* __restrict__ Wh, const float* __restrict__ bh) {
    int idx = blockIdx.x * blockDim.x + threadIdx.x;
    if (idx < 384 * 128) {
        int n = idx >> 7, c = idx & 127;
        const float* W = (n < 128) ? Wl : ((n < 256) ? Wsc : Wh);
        uint32_t h, l; tf32split(W[(n & 127) * 128 + c], h, l);
        g_Wstk_hi[idx] = h; g_Wstk_lo[idx] = l;
    }
    if (idx < 384) {
        const float* bb = (idx < 128) ? bl : ((idx < 256) ? bs : bh);
        g_bstk[idx] = bb[idx & 127];
    }
}

// ---------------- GRU gate fusion (writes split h) ----------------
__device__ __forceinline__ float sigm(float x) { return 1.f / (1.f + expf(-x)); }

__global__ void gru_gate(const float* __restrict__ gi, const float* __restrict__ gh,
                         const float* __restrict__ h0,
                         uint32_t* __restrict__ hhi, uint32_t* __restrict__ hlo) {
    int idx = blockIdx.x * blockDim.x + threadIdx.x;
    if (idx >= ROWS * 128) return;
    int m = idx >> 7, c = idx & 127;
    const float* gim = gi + (size_t)m * 384;
    const float* ghm = gh + (size_t)m * 384;
    float r = sigm(gim[c] + ghm[c]);
    float u = sigm(gim[128 + c] + ghm[128 + c]);
    float n = tanhf(gim[256 + c] + r * ghm[256 + c]);
    float v = (1.f - u) * n + u * h0[idx];
    uint32_t h, l; tf32split(v, h, l);
    hhi[idx] = h; hlo[idx] = l;
}

// ---------------- pair stage (writes split E) ----------------
__global__ void __launch_bounds__(512) pair_kernel(
    const float* __restrict__ UV, const float* __restrict__ Wa,
    const float* __restrict__ ba, const float* __restrict__ be,
    uint32_t* __restrict__ Ehi, uint32_t* __restrict__ Elo)
{
    extern __shared__ float smf[];
    float* Ub  = smf;
    float* Vb  = Ub + 16 * 512;
    float* Eb  = Vb + 16 * 512;
    float* was = Eb + 16 * 512;
    float* bes = was + 512;

    const int b = blockIdx.x;
    const int tid = threadIdx.x;

    for (int i = tid; i < 16 * 512; i += 512) {
        int k = i >> 9, t = i & 511;
        const float* row = UV + (size_t)(b * 16 + k) * 1024;
        Ub[i] = row[t];
        Vb[i] = row[512 + t];
        Eb[i] = 0.f;
    }
    was[tid & 511] = Wa[tid & 511];
    bes[tid & 511] = be[tid & 511];
    __syncthreads();

    const float ba0 = ba[0];
    const int wid = tid >> 5, lane = tid & 31;

    for (int p = wid; p < NPAIR; p += 16) {
        int ii = 0, rem = p, span = K_OBJ - 1;
        while (rem >= span) { rem -= span; ii++; span--; }
        int jj = ii + 1 + rem;

        const float* Ui = Ub + ii * 512;
        const float* Vj = Vb + jj * 512;
        float e[16];
        float dot = 0.f;
#pragma unroll
        for (int c = 0; c < 16; c++) {
            int t = lane + 32 * c;
            float x = Ui[t] + Vj[t] + bes[t];
            x = (x > 0.f) ? x : expm1f(x);
            e[c] = x;
            dot += x * was[t];
        }
#pragma unroll
        for (int o = 16; o > 0; o >>= 1) dot += __shfl_xor_sync(0xffffffffu, dot, o);
        float att = 1.f / (1.f + expf(-(dot + ba0)));

        float* Ei = Eb + ii * 512;
        float* Ej = Eb + jj * 512;
#pragma unroll
        for (int c = 0; c < 16; c++) {
            int t = lane + 32 * c;
            float w = att * e[c];
            atomicAdd(Ei + t, w);
            atomicAdd(Ej + t, w);
        }
    }
    __syncthreads();

    uint32_t* Eh = Ehi + (size_t)b * 16 * 512;
    uint32_t* El = Elo + (size_t)b * 16 * 512;
    for (int i = tid; i < 16 * 512; i += 512) {
        uint32_t h, l; tf32split(Eb[i], h, l);
        Eh[i] = h; El[i] = l;
    }
}

// ---------------- host launcher ----------------
extern "C" void kernel_launch(void* const* d_in, const int* in_sizes, int n_in,
                              void* d_out, int out_size)
{
    const float* z    = (const float*)d_in[0];
    const float* h0   = (const float*)d_in[1];
    const float* W_obj= (const float*)d_in[2];
    const float* b_obj= (const float*)d_in[3];
    const float* Wih  = (const float*)d_in[4];
    const float* bih  = (const float*)d_in[5];
    const float* Whh  = (const float*)d_in[6];
    const float* bhh  = (const float*)d_in[7];
    const float* We   = (const float*)d_in[8];
    const float* be   = (const float*)d_in[9];
    const float* Wa   = (const float*)d_in[10];
    const float* ba   = (const float*)d_in[11];
    const float* Wc   = (const float*)d_in[12];
    const float* bc   = (const float*)d_in[13];
    const float* Wl   = (const float*)d_in[14];
    const float* bl   = (const float*)d_in[15];
    const float* Wsc  = (const float*)d_in[16];
    const float* bs   = (const float*)d_in[17];
    const float* Wh   = (const float*)d_in[18];
    const float* bh   = (const float*)d_in[19];

    float* out1 = (float*)d_out;                 // [ROWS, 256] = concat(loc, scale)
    float* out2 = out1 + (size_t)ROWS * 256;     // [ROWS, 128] = h_out

    uint32_t *p_z_hi, *p_z_lo, *p_h0_hi, *p_h0_lo, *p_ze_hi, *p_ze_lo;
    uint32_t *p_h_hi, *p_h_lo, *p_E_hi, *p_E_lo, *p_rel_hi, *p_rel_lo;
    float *p_gi, *p_gh, *p_UV, *p_bstk;
    uint32_t *p_Wobj_hi, *p_Wobj_lo, *p_Wih_hi, *p_Wih_lo, *p_Whh_hi, *p_Whh_lo;
    uint32_t *p_WUV_hi, *p_WUV_lo, *p_WcE_hi, *p_WcE_lo, *p_Wstk_hi, *p_Wstk_lo;

    cudaGetSymbolAddress((void**)&p_z_hi,  g_z_hi);   cudaGetSymbolAddress((void**)&p_z_lo,  g_z_lo);
    cudaGetSymbolAddress((void**)&p_h0_hi, g_h0_hi);  cudaGetSymbolAddress((void**)&p_h0_lo, g_h0_lo);
    cudaGetSymbolAddress((void**)&p_ze_hi, g_ze_hi);  cudaGetSymbolAddress((void**)&p_ze_lo, g_ze_lo);
    cudaGetSymbolAddress((void**)&p_h_hi,  g_h_hi);   cudaGetSymbolAddress((void**)&p_h_lo,  g_h_lo);
    cudaGetSymbolAddress((void**)&p_E_hi,  g_E_hi);   cudaGetSymbolAddress((void**)&p_E_lo,  g_E_lo);
    cudaGetSymbolAddress((void**)&p_rel_hi,g_rel_hi); cudaGetSymbolAddress((void**)&p_rel_lo,g_rel_lo);
    cudaGetSymbolAddress((void**)&p_gi, g_gi);
    cudaGetSymbolAddress((void**)&p_gh, g_gh);
    cudaGetSymbolAddress((void**)&p_UV, g_UV);
    cudaGetSymbolAddress((void**)&p_bstk, g_bstk);
    cudaGetSymbolAddress((void**)&p_Wobj_hi, g_Wobj_hi); cudaGetSymbolAddress((void**)&p_Wobj_lo, g_Wobj_lo);
    cudaGetSymbolAddress((void**)&p_Wih_hi,  g_Wih_hi);  cudaGetSymbolAddress((void**)&p_Wih_lo,  g_Wih_lo);
    cudaGetSymbolAddress((void**)&p_Whh_hi,  g_Whh_hi);  cudaGetSymbolAddress((void**)&p_Whh_lo,  g_Whh_lo);
    cudaGetSymbolAddress((void**)&p_WUV_hi,  g_WUV_hi);  cudaGetSymbolAddress((void**)&p_WUV_lo,  g_WUV_lo);
    cudaGetSymbolAddress((void**)&p_WcE_hi,  g_WcE_hi);  cudaGetSymbolAddress((void**)&p_WcE_lo,  g_WcE_lo);
    cudaGetSymbolAddress((void**)&p_Wstk_hi, g_Wstk_hi); cudaGetSymbolAddress((void**)&p_Wstk_lo, g_Wstk_lo);

    const int SMEM_GEMM = 2 * STG_WORDS * 4;   // 81920
    cudaFuncSetAttribute(gemm_mma<1,1>, cudaFuncAttributeMaxDynamicSharedMemorySize, SMEM_GEMM);
    cudaFuncSetAttribute(gemm_mma<0,0>, cudaFuncAttributeMaxDynamicSharedMemorySize, SMEM_GEMM);
    cudaFuncSetAttribute(gemm_mma<0,1>, cudaFuncAttributeMaxDynamicSharedMemorySize, SMEM_GEMM);
    cudaFuncSetAttribute(gemm_mma<0,2>, cudaFuncAttributeMaxDynamicSharedMemorySize, SMEM_GEMM);

    // input + weight splits
    split_f32<<<(ROWS * 128 + 255) / 256, 256>>>(z, p_z_hi, p_z_lo, ROWS * 128);
    split_f32<<<(ROWS * 128 + 255) / 256, 256>>>(h0, p_h0_hi, p_h0_lo, ROWS * 128);
    split_f32<<<(256 * 128 + 255) / 256, 256>>>(W_obj, p_Wobj_hi, p_Wobj_lo, 256 * 128);
    split_f32<<<(384 * 256 + 255) / 256, 256>>>(Wih, p_Wih_hi, p_Wih_lo, 384 * 256);
    split_f32<<<(384 * 128 + 255) / 256, 256>>>(Whh, p_Whh_hi, p_Whh_lo, 384 * 128);
    prep_wuv <<<(1024 * 128 + 255) / 256, 256>>>(We);
    prep_wc  <<<(128 * 640 + 255) / 256, 256>>>(Wc);
    prep_wstk<<<(384 * 128 + 255) / 256, 256>>>(Wl, bl, Wsc, bs, Wh, bh);

    const int MB = ROWS / 128;   // 256

    // G1: z_embed = elu(z @ W_obj^T + b_obj) -> split  [ROWS, 256]
    gemm_mma<1,1><<<dim3(2, MB), 256, SMEM_GEMM>>>(
        p_z_hi, p_z_lo, 128, 128, nullptr, nullptr, 0,
        p_Wobj_hi, p_Wobj_lo, b_obj, nullptr, p_ze_hi, p_ze_lo, 256, nullptr, 128);
    // G2a: gi = z_embed @ Wih^T + bih  [ROWS, 384] f32
    gemm_mma<0,0><<<dim3(3, MB), 256, SMEM_GEMM>>>(
        p_ze_hi, p_ze_lo, 256, 256, nullptr, nullptr, 0,
        p_Wih_hi, p_Wih_lo, bih, p_gi, nullptr, nullptr, 384, nullptr, 256);
    // G2b: gh = h0 @ Whh^T + bhh  [ROWS, 384] f32
    gemm_mma<0,0><<<dim3(3, MB), 256, SMEM_GEMM>>>(
        p_h0_hi, p_h0_lo, 128, 128, nullptr, nullptr, 0,
        p_Whh_hi, p_Whh_lo, bhh, p_gh, nullptr, nullptr, 384, nullptr, 128);
    // GRU gates -> h (split)
    gru_gate<<<(ROWS * 128 + 255) / 256, 256>>>(p_gi, p_gh, h0, p_h_hi, p_h_lo);

    // G3: UV = h @ W_UV^T  [ROWS, 1024] f32
    gemm_mma<0,0><<<dim3(8, MB), 256, SMEM_GEMM>>>(
        p_h_hi, p_h_lo, 128, 128, nullptr, nullptr, 0,
        p_WUV_hi, p_WUV_lo, nullptr, p_UV, nullptr, nullptr, 1024, nullptr, 128);

    // pair stage -> E (split) [ROWS, 512]
    size_t psmem = (3 * 16 * 512 + 1024) * sizeof(float);
    cudaFuncSetAttribute(pair_kernel, cudaFuncAttributeMaxDynamicSharedMemorySize, (int)psmem);
    pair_kernel<<<B_SZ, 512, psmem>>>(p_UV, Wa, ba, be, p_E_hi, p_E_lo);

    // G4: rel = [h | E] @ WcE^T + bc -> split  [ROWS, 128], Kd=640
    gemm_mma<0,1><<<dim3(1, MB), 256, SMEM_GEMM>>>(
        p_h_hi, p_h_lo, 128, 128, p_E_hi, p_E_lo, 512,
        p_WcE_hi, p_WcE_lo, bc, nullptr, p_rel_hi, p_rel_lo, 128, nullptr, 640);

    // G5: [loc|scale|h_out] = rel @ Wstk^T + bstk, final split output
    gemm_mma<0,2><<<dim3(3, MB), 256, SMEM_GEMM>>>(
        p_rel_hi, p_rel_lo, 128, 128, nullptr, nullptr, 0,
        p_Wstk_hi, p_Wstk_lo, p_bstk, out1, nullptr, nullptr, 0, out2, 128);
}

// round 5
// speedup vs baseline: 1.4495x; 1.2670x over previous
#include <cuda_runtime.h>
#include <cuda_bf16.h>
#include <math.h>
#include <stdint.h>

#define B_SZ   2048
#define K_OBJ  16
#define ROWS   (B_SZ * K_OBJ)      // 32768
#define NPAIR  120

typedef __nv_bfloat16 bf16;

// ---------------- scratch (device globals; no allocation allowed) ----------------
// bf16-split activation buffers (hi/lo pairs)
__device__ __align__(16) bf16 g_z_hi  [(size_t)ROWS * 128];
__device__ __align__(16) bf16 g_z_lo  [(size_t)ROWS * 128];
__device__ __align__(16) bf16 g_h0_hi [(size_t)ROWS * 128];
__device__ __align__(16) bf16 g_h0_lo [(size_t)ROWS * 128];
__device__ __align__(16) bf16 g_ze_hi [(size_t)ROWS * 256];
__device__ __align__(16) bf16 g_ze_lo [(size_t)ROWS * 256];
__device__ __align__(16) bf16 g_h_hi  [(size_t)ROWS * 128];
__device__ __align__(16) bf16 g_h_lo  [(size_t)ROWS * 128];
__device__ __align__(16) bf16 g_E_hi  [(size_t)ROWS * 512];
__device__ __align__(16) bf16 g_E_lo  [(size_t)ROWS * 512];
__device__ __align__(16) bf16 g_rel_hi[(size_t)ROWS * 128];
__device__ __align__(16) bf16 g_rel_lo[(size_t)ROWS * 128];
// f32 intermediates consumed by elementwise kernels
__device__ __align__(16) float g_gi [(size_t)ROWS * 384];
__device__ __align__(16) float g_gh [(size_t)ROWS * 384];
__device__ __align__(16) float g_UV [(size_t)ROWS * 1024];
// split weights
__device__ __align__(16) bf16 g_Wobj_hi[256 * 128],  g_Wobj_lo[256 * 128];
__device__ __align__(16) bf16 g_Wih_hi [384 * 256],  g_Wih_lo [384 * 256];
__device__ __align__(16) bf16 g_Whh_hi [384 * 128],  g_Whh_lo [384 * 128];
__device__ __align__(16) bf16 g_WUV_hi [1024 * 128], g_WUV_lo [1024 * 128];
__device__ __align__(16) bf16 g_WcE_hi [128 * 640],  g_WcE_lo [128 * 640];
__device__ __align__(16) bf16 g_Wstk_hi[384 * 128],  g_Wstk_lo[384 * 128];
__device__ __align__(16) float g_bstk[384];

// ---------------- helpers ----------------
__device__ __forceinline__ void bf16split(float x, bf16& h, bf16& l) {
    h = __float2bfloat16_rn(x);
    l = __float2bfloat16_rn(x - __bfloat162float(h));
}

__device__ __forceinline__ uint32_t smem_u32(const void* p) {
    uint32_t a;
    asm("{ .reg .u64 t; cvta.to.shared.u64 t, %1; cvt.u32.u64 %0, t; }" : "=r"(a) : "l"(p));
    return a;
}

__device__ __forceinline__ void cp16(uint32_t dst, const void* src) {
    asm volatile("cp.async.ca.shared.global [%0], [%1], 16;" :: "r"(dst), "l"(src) : "memory");
}
#define CP_COMMIT() asm volatile("cp.async.commit_group;" ::: "memory")
#define CP_WAIT(n)  asm volatile("cp.async.wait_group %0;" :: "n"(n) : "memory")

__device__ __forceinline__ void mma16(float* d, const uint32_t* a, const uint32_t* b) {
    asm volatile(
        "mma.sync.aligned.m16n8k16.row.col.f32.bf16.bf16.f32 "
        "{%0,%1,%2,%3}, {%4,%5,%6,%7}, {%8,%9}, {%0,%1,%2,%3};"
        : "+f"(d[0]), "+f"(d[1]), "+f"(d[2]), "+f"(d[3])
        : "r"(a[0]), "r"(a[1]), "r"(a[2]), "r"(a[3]), "r"(b[0]), "r"(b[1]));
}

// ---------------- tensor-core bf16x3 NT GEMM, pre-split operands ----------------
// C[M,N] = act(X @ W^T + bias); X split at k1 between X1/X2; W [N,Kd] row-major bf16 hi/lo.
// CTA tile 128x128, K-slab 16, 2-stage cp.async pipeline. 8 warps, each 32(M)x64(N).
// smem per tile: 128 rows x 12 words (8 kpair words + pad4) = 6144 B; 4 tiles/stage; 2 stages = 49152 B.
// OUTM: 0 = f32 C; 1 = bf16-split (Chi, Clo); 2 = final f32 (n<256 -> C ld256, else C2 ld128).
#define PADW 12
#define STG_WORDS 6144     // 4 tiles * 128 * PADW
#define TILE_WORDS 1536    // 128 * PADW

template <int ACT, int OUTM>
__global__ void __launch_bounds__(256, 2) gemm_mma(
    const bf16* __restrict__ X1hi, const bf16* __restrict__ X1lo, int ld1, int k1,
    const bf16* __restrict__ X2hi, const bf16* __restrict__ X2lo, int ld2,
    const bf16* __restrict__ Whi, const bf16* __restrict__ Wlo,
    const float* __restrict__ bias,
    float* __restrict__ C, bf16* __restrict__ Chi, bf16* __restrict__ Clo,
    int ldc, float* __restrict__ C2, int Kd)
{
    extern __shared__ uint32_t smw[];
    const uint32_t sb = smem_u32(smw);

    const int tid = threadIdx.x;
    const int lane = tid & 31;
    const int wid = tid >> 5;
    const int warp_m = wid >> 1;
    const int warp_n = wid & 1;
    const int gid = lane >> 2;
    const int tig = lane & 3;
    const int bm = blockIdx.y * 128;
    const int bn = blockIdx.x * 128;

    float acc[2][8][4];
#pragma unroll
    for (int mi = 0; mi < 2; mi++)
#pragma unroll
        for (int nf = 0; nf < 8; nf++)
#pragma unroll
            for (int e = 0; e < 4; e++) acc[mi][nf][e] = 0.f;

    const int lm = tid >> 1;            // row 0..127
    const int lk = (tid & 1) * 8;       // k-elem offset 0 or 8
    const uint32_t so = (uint32_t)(lm * PADW + (tid & 1) * 4) * 4;

    auto load_slab = [&](int k0, int s) {
        const bf16 *ahi, *alo; int xld, xc;
        if (k0 < k1) { ahi = X1hi; alo = X1lo; xld = ld1; xc = k0; }
        else         { ahi = X2hi; alo = X2lo; xld = ld2; xc = k0 - k1; }
        const uint32_t st = sb + s * (STG_WORDS * 4);
        const size_t ga = (size_t)(bm + lm) * xld + xc + lk;
        const size_t gw = (size_t)(bn + lm) * Kd + k0 + lk;
        cp16(st + so,                       ahi + ga);
        cp16(st + TILE_WORDS * 4 + so,      alo + ga);
        cp16(st + TILE_WORDS * 8 + so,      Whi + gw);
        cp16(st + TILE_WORDS * 12 + so,     Wlo + gw);
    };

    int s = 0;
    load_slab(0, 0);
    CP_COMMIT();

#pragma unroll 1
    for (int k0 = 0; k0 < Kd; k0 += 16) {
        if (k0 + 16 < Kd) {
            load_slab(k0 + 16, s ^ 1);
            CP_COMMIT();
            CP_WAIT(1);
        } else {
            CP_WAIT(0);
        }
        __syncthreads();

        const uint32_t* sA  = smw + s * STG_WORDS;
        const uint32_t* sAl = sA + TILE_WORDS;
        const uint32_t* sB  = sA + 2 * TILE_WORDS;
        const uint32_t* sBl = sA + 3 * TILE_WORDS;

        uint32_t ah[2][4], al[2][4];
#pragma unroll
        for (int mi = 0; mi < 2; mi++) {
            int am = (warp_m * 32 + mi * 16 + gid) * PADW;
            ah[mi][0] = sA [am + tig];
            ah[mi][1] = sA [am + 8 * PADW + tig];
            ah[mi][2] = sA [am + tig + 4];
            ah[mi][3] = sA [am + 8 * PADW + tig + 4];
            al[mi][0] = sAl[am + tig];
            al[mi][1] = sAl[am + 8 * PADW + tig];
            al[mi][2] = sAl[am + tig + 4];
            al[mi][3] = sAl[am + 8 * PADW + tig + 4];
        }
        uint32_t bf[8][2];
#pragma unroll
        for (int nf = 0; nf < 8; nf++) {
            int an = (warp_n * 64 + nf * 8 + gid) * PADW;
            bf[nf][0] = sB[an + tig];
            bf[nf][1] = sB[an + tig + 4];
        }
#pragma unroll
        for (int mi = 0; mi < 2; mi++)
#pragma unroll
            for (int nf = 0; nf < 8; nf++) {
                mma16(acc[mi][nf], ah[mi], bf[nf]);
                mma16(acc[mi][nf], al[mi], bf[nf]);
            }
#pragma unroll
        for (int nf = 0; nf < 8; nf++) {
            int an = (warp_n * 64 + nf * 8 + gid) * PADW;
            bf[nf][0] = sBl[an + tig];
            bf[nf][1] = sBl[an + tig + 4];
        }
#pragma unroll
        for (int mi = 0; mi < 2; mi++)
#pragma unroll
            for (int nf = 0; nf < 8; nf++)
                mma16(acc[mi][nf], ah[mi], bf[nf]);

        __syncthreads();
        s ^= 1;
    }

    // ---- epilogue ----
    float* outp = C; int oldc = ldc, ncol0 = bn;
    if (OUTM == 2) {
        if (bn >= 256) { outp = C2; oldc = 128; ncol0 = bn - 256; }
        else           { outp = C;  oldc = 256; ncol0 = bn; }
    }

#pragma unroll
    for (int mi = 0; mi < 2; mi++) {
        int r0 = bm + warp_m * 32 + mi * 16 + gid;
#pragma unroll
        for (int nf = 0; nf < 8; nf++) {
            int cg = bn + warp_n * 64 + nf * 8 + tig * 2;
            int cl = ncol0 + warp_n * 64 + nf * 8 + tig * 2;
            float b0 = 0.f, b1 = 0.f;
            if (bias) { float2 bv = *(const float2*)(bias + cg); b0 = bv.x; b1 = bv.y; }
            float v00 = acc[mi][nf][0] + b0;
            float v01 = acc[mi][nf][1] + b1;
            float v10 = acc[mi][nf][2] + b0;
            float v11 = acc[mi][nf][3] + b1;
            if (ACT == 1) {
                v00 = (v00 > 0.f) ? v00 : expm1f(v00);
                v01 = (v01 > 0.f) ? v01 : expm1f(v01);
                v10 = (v10 > 0.f) ? v10 : expm1f(v10);
                v11 = (v11 > 0.f) ? v11 : expm1f(v11);
            }
            if (OUTM == 1) {
                bf16 h, l;
                __nv_bfloat162 ph0, pl0, ph1, pl1;
                bf16split(v00, h, l); ph0.x = h; pl0.x = l;
                bf16split(v01, h, l); ph0.y = h; pl0.y = l;
                bf16split(v10, h, l); ph1.x = h; pl1.x = l;
                bf16split(v11, h, l); ph1.y = h; pl1.y = l;
                *(__nv_bfloat162*)(Chi + (size_t)r0 * ldc + cl)       = ph0;
                *(__nv_bfloat162*)(Clo + (size_t)r0 * ldc + cl)       = pl0;
                *(__nv_bfloat162*)(Chi + (size_t)(r0 + 8) * ldc + cl) = ph1;
                *(__nv_bfloat162*)(Clo + (size_t)(r0 + 8) * ldc + cl) = pl1;
            } else {
                *(float2*)(outp + (size_t)r0 * oldc + cl)       = make_float2(v00, v01);
                *(float2*)(outp + (size_t)(r0 + 8) * oldc + cl) = make_float2(v10, v11);
            }
        }
    }
}

// ---------------- split / prep kernels ----------------
__global__ void split_f32(const float* __restrict__ src, bf16* __restrict__ hi,
                          bf16* __restrict__ lo, int n) {
    int idx = blockIdx.x * blockDim.x + threadIdx.x;
    if (idx >= n) return;
    bf16 h, l;
    bf16split(src[idx], h, l);
    hi[idx] = h; lo[idx] = l;
}

__global__ void prep_wuv(const float* __restrict__ We) {
    int idx = blockIdx.x * blockDim.x + threadIdx.x;
    if (idx >= 1024 * 128) return;
    int n = idx >> 7, c = idx & 127;
    float v;
    if (n < 512) v = We[n * 512 + c] + We[n * 512 + 128 + c];
    else {
        int nn = n - 512;
        v = We[nn * 512 + 256 + c] + We[nn * 512 + 384 + c];
    }
    bf16 h, l; bf16split(v, h, l);
    g_WUV_hi[idx] = h; g_WUV_lo[idx] = l;
}

__global__ void prep_wc(const float* __restrict__ Wc) {
    int idx = blockIdx.x * blockDim.x + threadIdx.x;
    if (idx >= 128 * 640) return;
    int n = idx / 640, c = idx % 640;
    float v = (c < 128) ? (Wc[n * 768 + c] + Wc[n * 768 + 128 + c])
                        : Wc[n * 768 + 128 + c];
    bf16 h, l; bf16split(v, h, l);
    g_WcE_hi[idx] = h; g_WcE_lo[idx] = l;
}

__global__ void prep_wstk(const float* __restrict__ Wl, const float* __restrict__ bl,
                          const float* __restrict__ Wsc, const float* __restrict__ bs,
                          const float* __restrict__ Wh, const float* __restrict__ bh) {
    int idx = blockIdx.x * blockDim.x + threadIdx.x;
    if (idx < 384 * 128) {
        int n = idx >> 7, c = idx & 127;
        const float* W = (n < 128) ? Wl : ((n < 256) ? Wsc : Wh);
        bf16 h, l; bf16split(W[(n & 127) * 128 + c], h, l);
        g_Wstk_hi[idx] = h; g_Wstk_lo[idx] = l;
    }
    if (idx < 384) {
        const float* bb = (idx < 128) ? bl : ((idx < 256) ? bs : bh);
        g_bstk[idx] = bb[idx & 127];
    }
}

// ---------------- GRU gate fusion (writes split h) ----------------
__device__ __forceinline__ float sigm(float x) { return 1.f / (1.f + expf(-x)); }

__global__ void gru_gate(const float* __restrict__ gi, const float* __restrict__ gh,
                         const float* __restrict__ h0,
                         bf16* __restrict__ hhi, bf16* __restrict__ hlo) {
    int idx = blockIdx.x * blockDim.x + threadIdx.x;
    if (idx >= ROWS * 128) return;
    int m = idx >> 7, c = idx & 127;
    const float* gim = gi + (size_t)m * 384;
    const float* ghm = gh + (size_t)m * 384;
    float r = sigm(gim[c] + ghm[c]);
    float u = sigm(gim[128 + c] + ghm[128 + c]);
    float n = tanhf(gim[256 + c] + r * ghm[256 + c]);
    float v = (1.f - u) * n + u * h0[idx];
    bf16 h, l; bf16split(v, h, l);
    hhi[idx] = h; hlo[idx] = l;
}

// ---------------- pair stage (writes split E) ----------------
__global__ void __launch_bounds__(512) pair_kernel(
    const float* __restrict__ UV, const float* __restrict__ Wa,
    const float* __restrict__ ba, const float* __restrict__ be,
    bf16* __restrict__ Ehi, bf16* __restrict__ Elo)
{
    extern __shared__ float smf[];
    float* Ub  = smf;
    float* Vb  = Ub + 16 * 512;
    float* Eb  = Vb + 16 * 512;
    float* was = Eb + 16 * 512;
    float* bes = was + 512;

    const int b = blockIdx.x;
    const int tid = threadIdx.x;

    for (int i = tid; i < 16 * 512; i += 512) {
        int k = i >> 9, t = i & 511;
        const float* row = UV + (size_t)(b * 16 + k) * 1024;
        Ub[i] = row[t];
        Vb[i] = row[512 + t];
        Eb[i] = 0.f;
    }
    was[tid & 511] = Wa[tid & 511];
    bes[tid & 511] = be[tid & 511];
    __syncthreads();

    const float ba0 = ba[0];
    const int wid = tid >> 5, lane = tid & 31;

    for (int p = wid; p < NPAIR; p += 16) {
        int ii = 0, rem = p, span = K_OBJ - 1;
        while (rem >= span) { rem -= span; ii++; span--; }
        int jj = ii + 1 + rem;

        const float* Ui = Ub + ii * 512;
        const float* Vj = Vb + jj * 512;
        float e[16];
        float dot = 0.f;
#pragma unroll
        for (int c = 0; c < 16; c++) {
            int t = lane + 32 * c;
            float x = Ui[t] + Vj[t] + bes[t];
            x = (x > 0.f) ? x : expm1f(x);
            e[c] = x;
            dot += x * was[t];
        }
#pragma unroll
        for (int o = 16; o > 0; o >>= 1) dot += __shfl_xor_sync(0xffffffffu, dot, o);
        float att = 1.f / (1.f + expf(-(dot + ba0)));

        float* Ei = Eb + ii * 512;
        float* Ej = Eb + jj * 512;
#pragma unroll
        for (int c = 0; c < 16; c++) {
            int t = lane + 32 * c;
            float w = att * e[c];
            atomicAdd(Ei + t, w);
            atomicAdd(Ej + t, w);
        }
    }
    __syncthreads();

    bf16* Eh = Ehi + (size_t)b * 16 * 512;
    bf16* El = Elo + (size_t)b * 16 * 512;
    for (int i = tid; i < 16 * 512; i += 512) {
        bf16 h, l; bf16split(Eb[i], h, l);
        Eh[i] = h; El[i] = l;
    }
}

// ---------------- host launcher ----------------
extern "C" void kernel_launch(void* const* d_in, const int* in_sizes, int n_in,
                              void* d_out, int out_size)
{
    const float* z    = (const float*)d_in[0];
    const float* h0   = (const float*)d_in[1];
    const float* W_obj= (const float*)d_in[2];
    const float* b_obj= (const float*)d_in[3];
    const float* Wih  = (const float*)d_in[4];
    const float* bih  = (const float*)d_in[5];
    const float* Whh  = (const float*)d_in[6];
    const float* bhh  = (const float*)d_in[7];
    const float* We   = (const float*)d_in[8];
    const float* be   = (const float*)d_in[9];
    const float* Wa   = (const float*)d_in[10];
    const float* ba   = (const float*)d_in[11];
    const float* Wc   = (const float*)d_in[12];
    const float* bc   = (const float*)d_in[13];
    const float* Wl   = (const float*)d_in[14];
    const float* bl   = (const float*)d_in[15];
    const float* Wsc  = (const float*)d_in[16];
    const float* bs   = (const float*)d_in[17];
    const float* Wh   = (const float*)d_in[18];
    const float* bh   = (const float*)d_in[19];

    float* out1 = (float*)d_out;                 // [ROWS, 256] = concat(loc, scale)
    float* out2 = out1 + (size_t)ROWS * 256;     // [ROWS, 128] = h_out

    bf16 *p_z_hi, *p_z_lo, *p_h0_hi, *p_h0_lo, *p_ze_hi, *p_ze_lo;
    bf16 *p_h_hi, *p_h_lo, *p_E_hi, *p_E_lo, *p_rel_hi, *p_rel_lo;
    float *p_gi, *p_gh, *p_UV, *p_bstk;
    bf16 *p_Wobj_hi, *p_Wobj_lo, *p_Wih_hi, *p_Wih_lo, *p_Whh_hi, *p_Whh_lo;
    bf16 *p_WUV_hi, *p_WUV_lo, *p_WcE_hi, *p_WcE_lo, *p_Wstk_hi, *p_Wstk_lo;

    cudaGetSymbolAddress((void**)&p_z_hi,  g_z_hi);   cudaGetSymbolAddress((void**)&p_z_lo,  g_z_lo);
    cudaGetSymbolAddress((void**)&p_h0_hi, g_h0_hi);  cudaGetSymbolAddress((void**)&p_h0_lo, g_h0_lo);
    cudaGetSymbolAddress((void**)&p_ze_hi, g_ze_hi);  cudaGetSymbolAddress((void**)&p_ze_lo, g_ze_lo);
    cudaGetSymbolAddress((void**)&p_h_hi,  g_h_hi);   cudaGetSymbolAddress((void**)&p_h_lo,  g_h_lo);
    cudaGetSymbolAddress((void**)&p_E_hi,  g_E_hi);   cudaGetSymbolAddress((void**)&p_E_lo,  g_E_lo);
    cudaGetSymbolAddress((void**)&p_rel_hi,g_rel_hi); cudaGetSymbolAddress((void**)&p_rel_lo,g_rel_lo);
    cudaGetSymbolAddress((void**)&p_gi, g_gi);
    cudaGetSymbolAddress((void**)&p_gh, g_gh);
    cudaGetSymbolAddress((void**)&p_UV, g_UV);
    cudaGetSymbolAddress((void**)&p_bstk, g_bstk);
    cudaGetSymbolAddress((void**)&p_Wobj_hi, g_Wobj_hi); cudaGetSymbolAddress((void**)&p_Wobj_lo, g_Wobj_lo);
    cudaGetSymbolAddress((void**)&p_Wih_hi,  g_Wih_hi);  cudaGetSymbolAddress((void**)&p_Wih_lo,  g_Wih_lo);
    cudaGetSymbolAddress((void**)&p_Whh_hi,  g_Whh_hi);  cudaGetSymbolAddress((void**)&p_Whh_lo,  g_Whh_lo);
    cudaGetSymbolAddress((void**)&p_WUV_hi,  g_WUV_hi);  cudaGetSymbolAddress((void**)&p_WUV_lo,  g_WUV_lo);
    cudaGetSymbolAddress((void**)&p_WcE_hi,  g_WcE_hi);  cudaGetSymbolAddress((void**)&p_WcE_lo,  g_WcE_lo);
    cudaGetSymbolAddress((void**)&p_Wstk_hi, g_Wstk_hi); cudaGetSymbolAddress((void**)&p_Wstk_lo, g_Wstk_lo);

    const int SMEM_GEMM = 2 * STG_WORDS * 4;   // 49152
    cudaFuncSetAttribute(gemm_mma<1,1>, cudaFuncAttributeMaxDynamicSharedMemorySize, SMEM_GEMM);
    cudaFuncSetAttribute(gemm_mma<0,0>, cudaFuncAttributeMaxDynamicSharedMemorySize, SMEM_GEMM);
    cudaFuncSetAttribute(gemm_mma<0,1>, cudaFuncAttributeMaxDynamicSharedMemorySize, SMEM_GEMM);
    cudaFuncSetAttribute(gemm_mma<0,2>, cudaFuncAttributeMaxDynamicSharedMemorySize, SMEM_GEMM);

    // input + weight splits
    split_f32<<<(ROWS * 128 + 255) / 256, 256>>>(z, p_z_hi, p_z_lo, ROWS * 128);
    split_f32<<<(ROWS * 128 + 255) / 256, 256>>>(h0, p_h0_hi, p_h0_lo, ROWS * 128);
    split_f32<<<(256 * 128 + 255) / 256, 256>>>(W_obj, p_Wobj_hi, p_Wobj_lo, 256 * 128);
    split_f32<<<(384 * 256 + 255) / 256, 256>>>(Wih, p_Wih_hi, p_Wih_lo, 384 * 256);
    split_f32<<<(384 * 128 + 255) / 256, 256>>>(Whh, p_Whh_hi, p_Whh_lo, 384 * 128);
    prep_wuv <<<(1024 * 128 + 255) / 256, 256>>>(We);
    prep_wc  <<<(128 * 640 + 255) / 256, 256>>>(Wc);
    prep_wstk<<<(384 * 128 + 255) / 256, 256>>>(Wl, bl, Wsc, bs, Wh, bh);

    const int MB = ROWS / 128;   // 256

    // G1: z_embed = elu(z @ W_obj^T + b_obj) -> split  [ROWS, 256]
    gemm_mma<1,1><<<dim3(2, MB), 256, SMEM_GEMM>>>(
        p_z_hi, p_z_lo, 128, 128, nullptr, nullptr, 0,
        p_Wobj_hi, p_Wobj_lo, b_obj, nullptr, p_ze_hi, p_ze_lo, 256, nullptr, 128);
    // G2a: gi = z_embed @ Wih^T + bih  [ROWS, 384] f32
    gemm_mma<0,0><<<dim3(3, MB), 256, SMEM_GEMM>>>(
        p_ze_hi, p_ze_lo, 256, 256, nullptr, nullptr, 0,
        p_Wih_hi, p_Wih_lo, bih, p_gi, nullptr, nullptr, 384, nullptr, 256);
    // G2b: gh = h0 @ Whh^T + bhh  [ROWS, 384] f32
    gemm_mma<0,0><<<dim3(3, MB), 256, SMEM_GEMM>>>(
        p_h0_hi, p_h0_lo, 128, 128, nullptr, nullptr, 0,
        p_Whh_hi, p_Whh_lo, bhh, p_gh, nullptr, nullptr, 384, nullptr, 128);
    // GRU gates -> h (split)
    gru_gate<<<(ROWS * 128 + 255) / 256, 256>>>(p_gi, p_gh, h0, p_h_hi, p_h_lo);

    // G3: UV = h @ W_UV^T  [ROWS, 1024] f32
    gemm_mma<0,0><<<dim3(8, MB), 256, SMEM_GEMM>>>(
        p_h_hi, p_h_lo, 128, 128, nullptr, nullptr, 0,
        p_WUV_hi, p_WUV_lo, nullptr, p_UV, nullptr, nullptr, 1024, nullptr, 128);

    // pair stage -> E (split) [ROWS, 512]
    size_t psmem = (3 * 16 * 512 + 1024) * sizeof(float);
    cudaFuncSetAttribute(pair_kernel, cudaFuncAttributeMaxDynamicSharedMemorySize, (int)psmem);
    pair_kernel<<<B_SZ, 512, psmem>>>(p_UV, Wa, ba, be, p_E_hi, p_E_lo);

    // G4: rel = [h | E] @ WcE^T + bc -> split  [ROWS, 128], Kd=640
    gemm_mma<0,1><<<dim3(1, MB), 256, SMEM_GEMM>>>(
        p_h_hi, p_h_lo, 128, 128, p_E_hi, p_E_lo, 512,
        p_WcE_hi, p_WcE_lo, bc, nullptr, p_rel_hi, p_rel_lo, 128, nullptr, 640);

    // G5: [loc|scale|h_out] = rel @ Wstk^T + bstk, final f32 split outputs
    gemm_mma<0,2><<<dim3(3, MB), 256, SMEM_GEMM>>>(
        p_rel_hi, p_rel_lo, 128, 128, nullptr, nullptr, 0,
        p_Wstk_hi, p_Wstk_lo, p_bstk, out1, nullptr, nullptr, 0, out2, 128);
}